// round 1
// baseline (speedup 1.0000x reference)
#include <cuda_runtime.h>

// ---------------- problem constants ----------------
#define HW        512
#define PLANES    48          // 16 batch * 3 channels
#define NPIX      12582912.0  // 48*512*512
#define TW        64
#define TH        32
#define SW        74          // TW + 10
#define SH        42          // TH + 10
#define SSTR      76          // padded smem row stride (floats)
#define NTHREADS  320

#define C1F 0.0001f
#define C2F 0.0009f

// Gaussian(sigma=1.5) centered at 5.5, normalized — computed in double, literal
// so ptxas emits FFMA-imm (rt_SMSP=1, 2x throughput vs 3-reg FFMA).
__device__ __constant__ const float GW_unused[1] = {0}; // keep nvcc happy about unused warnings
#define G0  0.00032030f
#define G1  0.00295566f
#define G2  0.01748770f
#define G3  0.06634250f
#define G4  0.16137290f
#define G5  0.25168100f

__device__ static const float GW[11] = {G0, G1, G2, G3, G4, G5, G5, G4, G3, G2, G1};

__device__ double g_accum;

__global__ void ssim_zero_kernel() { g_accum = 0.0; }

__global__ void ssim_finalize_kernel(float* out) {
    out[0] = (float)(g_accum * (1.0 / NPIX));
}

#define SIN(q, r, c)  s_in[((q) * SH + (r)) * SSTR + (c)]
#define SMID(q, r, c) s_mid[((q) * TH + (r)) * SSTR + (c)]

__global__ void __launch_bounds__(NTHREADS, 2)
ssim_main_kernel(const float* __restrict__ img1, const float* __restrict__ img2) {
    extern __shared__ float smem[];
    float* s_in  = smem;                    // 5 * SH * SSTR
    float* s_mid = smem + 5 * SH * SSTR;    // 5 * TH * SSTR

    const int tid   = threadIdx.x;
    const int plane = blockIdx.z;
    const int x0    = blockIdx.x * TW;
    const int y0    = blockIdx.y * TH;

    const float* __restrict__ p1 = img1 + (size_t)plane * HW * HW;
    const float* __restrict__ p2 = img2 + (size_t)plane * HW * HW;

    // ---------- Phase 1: load halo tiles + products ----------
    for (int i = tid; i < SH * SW; i += NTHREADS) {
        const int r  = i / SW;
        const int c  = i - r * SW;
        const int gy = y0 - 5 + r;
        const int gx = x0 - 5 + c;
        float a = 0.f, b = 0.f;
        if ((unsigned)gy < (unsigned)HW && (unsigned)gx < (unsigned)HW) {
            const int gi = gy * HW + gx;
            a = p1[gi];
            b = p2[gi];
        }
        SIN(0, r, c) = a;
        SIN(1, r, c) = b;
        SIN(2, r, c) = a * a;
        SIN(3, r, c) = b * b;
        SIN(4, r, c) = a * b;
    }
    __syncthreads();

    // ---------- Phase 2: vertical 11-tap conv (register-blocked, R=8 rows) ----
    if (tid < 296) {                 // 74 columns * 4 row-groups
        const int x  = tid % 74;
        const int rg = tid / 74;
        const int yb = rg * 8;

        // group A: quantities 0,1
        {
            float a0[8], a1[8];
#pragma unroll
            for (int r = 0; r < 8; ++r) { a0[r] = 0.f; a1[r] = 0.f; }
#pragma unroll
            for (int jj = 0; jj < 18; ++jj) {
                const float va = SIN(0, yb + jj, x);
                const float vb = SIN(1, yb + jj, x);
#pragma unroll
                for (int r = 0; r < 8; ++r) {
                    const int j = jj - r;
                    if (0 <= j && j < 11) {
                        a0[r] = fmaf(GW[j], va, a0[r]);
                        a1[r] = fmaf(GW[j], vb, a1[r]);
                    }
                }
            }
#pragma unroll
            for (int r = 0; r < 8; ++r) {
                SMID(0, yb + r, x) = a0[r];
                SMID(1, yb + r, x) = a1[r];
            }
        }
        // group B: quantities 2,3,4
        {
            float a2[8], a3[8], a4[8];
#pragma unroll
            for (int r = 0; r < 8; ++r) { a2[r] = 0.f; a3[r] = 0.f; a4[r] = 0.f; }
#pragma unroll
            for (int jj = 0; jj < 18; ++jj) {
                const float vaa = SIN(2, yb + jj, x);
                const float vbb = SIN(3, yb + jj, x);
                const float vab = SIN(4, yb + jj, x);
#pragma unroll
                for (int r = 0; r < 8; ++r) {
                    const int j = jj - r;
                    if (0 <= j && j < 11) {
                        a2[r] = fmaf(GW[j], vaa, a2[r]);
                        a3[r] = fmaf(GW[j], vbb, a3[r]);
                        a4[r] = fmaf(GW[j], vab, a4[r]);
                    }
                }
            }
#pragma unroll
            for (int r = 0; r < 8; ++r) {
                SMID(2, yb + r, x) = a2[r];
                SMID(3, yb + r, x) = a3[r];
                SMID(4, yb + r, x) = a4[r];
            }
        }
    }
    __syncthreads();

    // ---------- Phase 3: horizontal 11-tap conv + SSIM ----------
    float lsum = 0.f;
    if (tid < 256) {                  // 32 rows * 8 column-groups of 8
        const int y  = tid >> 3;
        const int xb = (tid & 7) * 8;

        float o[5][8];
#pragma unroll
        for (int q = 0; q < 5; ++q) {
            const float4* vp = reinterpret_cast<const float4*>(&SMID(q, y, xb));
            float m[20];
#pragma unroll
            for (int k = 0; k < 5; ++k) {
                const float4 v = vp[k];
                m[4 * k + 0] = v.x;
                m[4 * k + 1] = v.y;
                m[4 * k + 2] = v.z;
                m[4 * k + 3] = v.w;
            }
#pragma unroll
            for (int r = 0; r < 8; ++r) {
                float s = GW[0] * m[r];
#pragma unroll
                for (int i = 1; i < 11; ++i) s = fmaf(GW[i], m[r + i], s);
                o[q][r] = s;
            }
        }
#pragma unroll
        for (int r = 0; r < 8; ++r) {
            const float mu1 = o[0][r], mu2 = o[1][r];
            const float e11 = o[2][r], e22 = o[3][r], e12 = o[4][r];
            const float m11 = mu1 * mu1;
            const float m22 = mu2 * mu2;
            const float m12 = mu1 * mu2;
            const float s1  = e11 - m11;
            const float s2  = e22 - m22;
            const float s12 = e12 - m12;
            const float num = fmaf(2.f, m12, C1F) * fmaf(2.f, s12, C2F);
            const float den = (m11 + m22 + C1F) * (s1 + s2 + C2F);
            lsum += __fdividef(num, den);
        }
    }

    // ---------- Reduction ----------
#pragma unroll
    for (int off = 16; off > 0; off >>= 1)
        lsum += __shfl_down_sync(0xffffffffu, lsum, off);

    __shared__ float warp_sums[NTHREADS / 32];
    const int wid  = tid >> 5;
    const int lane = tid & 31;
    if (lane == 0) warp_sums[wid] = lsum;
    __syncthreads();
    if (tid == 0) {
        float s = 0.f;
#pragma unroll
        for (int w = 0; w < NTHREADS / 32; ++w) s += warp_sums[w];
        atomicAdd(&g_accum, (double)s);
    }
}

extern "C" void kernel_launch(void* const* d_in, const int* in_sizes, int n_in,
                              void* d_out, int out_size) {
    const float* img1 = (const float*)d_in[0];
    const float* img2 = (const float*)d_in[1];
    float* out = (float*)d_out;

    const int smem_bytes = (5 * SH * SSTR + 5 * TH * SSTR) * (int)sizeof(float); // 112480
    cudaFuncSetAttribute(ssim_main_kernel,
                         cudaFuncAttributeMaxDynamicSharedMemorySize, smem_bytes);

    ssim_zero_kernel<<<1, 1>>>();
    dim3 grid(HW / TW, HW / TH, PLANES);   // 8 x 16 x 48
    ssim_main_kernel<<<grid, NTHREADS, smem_bytes>>>(img1, img2);
    ssim_finalize_kernel<<<1, 1>>>(out);
}

// round 3
// speedup vs baseline: 1.5914x; 1.5914x over previous
#include <cuda_runtime.h>

// ---------------- problem constants ----------------
#define HW        512
#define PLANES    48          // 16 batch * 3 channels
#define NPIX      12582912.0  // 48*512*512
#define TW        64
#define TH        32
#define SW        74          // TW + 10
#define SH        42          // TH + 10
#define SSTR      76          // padded smem row stride (floats)
#define NTHREADS  320
#define NBLOCKS   6144        // 8*16*48

#define C1F 0.0001f
#define C2F 0.0009f

// Gaussian(sigma=1.5) centered at 5.5, normalized. __device__ constexpr so it
// is valid in device code AND every tap folds to an FFMA immediate
// (imm-form rt_SMSP=1, 2x vs 3-reg FFMA).
__device__ constexpr float GW[11] = {
    0.00032028f, 0.00295570f, 0.01748600f, 0.06634300f, 0.16137400f,
    0.25168200f, 0.25168200f, 0.16137400f, 0.06634300f, 0.01748600f,
    0.00295570f
};

__device__ double g_part[NBLOCKS];

__global__ void ssim_finalize_kernel(float* __restrict__ out) {
    __shared__ double sd[256];
    double s = 0.0;
    for (int i = threadIdx.x; i < NBLOCKS; i += 256) s += g_part[i];
    sd[threadIdx.x] = s;
    __syncthreads();
#pragma unroll
    for (int off = 128; off > 0; off >>= 1) {
        if (threadIdx.x < off) sd[threadIdx.x] += sd[threadIdx.x + off];
        __syncthreads();
    }
    if (threadIdx.x == 0) out[0] = (float)(sd[0] * (1.0 / NPIX));
}

// FMA-only reciprocal: magic-constant seed + 3 Newton steps (e -> e^8 ~ 1e-8).
// Avoids MUFU.RCP (rt_SMSP=8, would be a ~90us chip-wide floor at 12.6M divides).
__device__ __forceinline__ float fast_rcp(float d) {
    float r = __int_as_float(0x7EF311C3 - __float_as_int(d));
#pragma unroll
    for (int it = 0; it < 3; ++it) {
        float t = fmaf(-d, r, 1.0f);
        r = fmaf(r, t, r);
    }
    return r;
}

#define SIN1(r, c)    s_in1[(r) * SSTR + (c)]
#define SIN2(r, c)    s_in2[(r) * SSTR + (c)]
#define SMID(q, r, c) s_mid[((q) * TH + (r)) * SSTR + (c)]

__global__ void __launch_bounds__(NTHREADS, 2)
ssim_main_kernel(const float* __restrict__ img1, const float* __restrict__ img2) {
    extern __shared__ float smem[];
    float* s_in1 = smem;                         // SH * SSTR
    float* s_in2 = smem + SH * SSTR;             // SH * SSTR
    float* s_mid = smem + 2 * SH * SSTR;         // 5 * TH * SSTR

    const int tid   = threadIdx.x;
    const int plane = blockIdx.z;
    const int x0    = blockIdx.x * TW;
    const int y0    = blockIdx.y * TH;

    const float* __restrict__ p1 = img1 + (size_t)plane * HW * HW;
    const float* __restrict__ p2 = img2 + (size_t)plane * HW * HW;

    // ---------- Phase 1: load halo tiles (zero-padded) ----------
#pragma unroll
    for (int ii = 0; ii < (SH * SW + NTHREADS - 1) / NTHREADS; ++ii) {
        const int i = tid + ii * NTHREADS;
        if (i < SH * SW) {
            const int r  = i / SW;
            const int c  = i - r * SW;
            const int gy = y0 - 5 + r;
            const int gx = x0 - 5 + c;
            float a = 0.f, b = 0.f;
            if ((unsigned)gy < (unsigned)HW && (unsigned)gx < (unsigned)HW) {
                const int gi = gy * HW + gx;
                a = p1[gi];
                b = p2[gi];
            }
            SIN1(r, c) = a;
            SIN2(r, c) = b;
        }
    }
    __syncthreads();

    // ---------- Phase 2: vertical 11-tap conv, 5 quantities fused ----------
    // products a*a, b*b, a*b computed on the fly (cheap MULs, saves smem+LDS)
    if (tid < 296) {                 // 74 columns * 4 row-groups of 8
        const int x  = tid % 74;
        const int yb = (tid / 74) * 8;

        float a0[8], a1[8], a2[8], a3[8], a4[8];
#pragma unroll
        for (int r = 0; r < 8; ++r) {
            a0[r] = 0.f; a1[r] = 0.f; a2[r] = 0.f; a3[r] = 0.f; a4[r] = 0.f;
        }
#pragma unroll
        for (int jj = 0; jj < 18; ++jj) {
            const float va  = SIN1(yb + jj, x);
            const float vb  = SIN2(yb + jj, x);
            const float vaa = va * va;
            const float vbb = vb * vb;
            const float vab = va * vb;
#pragma unroll
            for (int r = 0; r < 8; ++r) {
                const int j = jj - r;
                if (0 <= j && j < 11) {
                    a0[r] = fmaf(GW[j], va,  a0[r]);
                    a1[r] = fmaf(GW[j], vb,  a1[r]);
                    a2[r] = fmaf(GW[j], vaa, a2[r]);
                    a3[r] = fmaf(GW[j], vbb, a3[r]);
                    a4[r] = fmaf(GW[j], vab, a4[r]);
                }
            }
        }
#pragma unroll
        for (int r = 0; r < 8; ++r) {
            SMID(0, yb + r, x) = a0[r];
            SMID(1, yb + r, x) = a1[r];
            SMID(2, yb + r, x) = a2[r];
            SMID(3, yb + r, x) = a3[r];
            SMID(4, yb + r, x) = a4[r];
        }
    }
    __syncthreads();

    // ---------- Phase 3: horizontal 11-tap conv + SSIM ----------
    float lsum = 0.f;
    if (tid < 256) {                  // 32 rows * 8 column-groups of 8
        const int y  = tid >> 3;
        const int xb = (tid & 7) * 8;

        float o[5][8];
#pragma unroll
        for (int q = 0; q < 5; ++q) {
            const float4* vp = reinterpret_cast<const float4*>(&SMID(q, y, xb));
            float m[20];
#pragma unroll
            for (int k = 0; k < 5; ++k) {
                const float4 v = vp[k];
                m[4 * k + 0] = v.x;
                m[4 * k + 1] = v.y;
                m[4 * k + 2] = v.z;
                m[4 * k + 3] = v.w;
            }
#pragma unroll
            for (int r = 0; r < 8; ++r) {
                float s = GW[0] * m[r];
#pragma unroll
                for (int i = 1; i < 11; ++i) s = fmaf(GW[i], m[r + i], s);
                o[q][r] = s;
            }
        }
#pragma unroll
        for (int r = 0; r < 8; ++r) {
            const float mu1 = o[0][r], mu2 = o[1][r];
            const float e11 = o[2][r], e22 = o[3][r], e12 = o[4][r];
            const float m11 = mu1 * mu1;
            const float m22 = mu2 * mu2;
            const float m12 = mu1 * mu2;
            const float s1  = e11 - m11;
            const float s2  = e22 - m22;
            const float s12 = e12 - m12;
            const float num = fmaf(2.f, m12, C1F) * fmaf(2.f, s12, C2F);
            const float den = (m11 + m22 + C1F) * (s1 + s2 + C2F);
            lsum = fmaf(num, fast_rcp(den), lsum);
        }
    }

    // ---------- Reduction ----------
#pragma unroll
    for (int off = 16; off > 0; off >>= 1)
        lsum += __shfl_down_sync(0xffffffffu, lsum, off);

    __shared__ float warp_sums[NTHREADS / 32];
    const int wid  = tid >> 5;
    const int lane = tid & 31;
    if (lane == 0) warp_sums[wid] = lsum;
    __syncthreads();
    if (tid == 0) {
        float s = 0.f;
#pragma unroll
        for (int w = 0; w < NTHREADS / 32; ++w) s += warp_sums[w];
        const int bid = (blockIdx.z * gridDim.y + blockIdx.y) * gridDim.x + blockIdx.x;
        g_part[bid] = (double)s;
    }
}

extern "C" void kernel_launch(void* const* d_in, const int* in_sizes, int n_in,
                              void* d_out, int out_size) {
    const float* img1 = (const float*)d_in[0];
    const float* img2 = (const float*)d_in[1];
    float* out = (float*)d_out;

    const int smem_bytes = (2 * SH * SSTR + 5 * TH * SSTR) * (int)sizeof(float); // 74176
    cudaFuncSetAttribute(ssim_main_kernel,
                         cudaFuncAttributeMaxDynamicSharedMemorySize, smem_bytes);

    dim3 grid(HW / TW, HW / TH, PLANES);   // 8 x 16 x 48
    ssim_main_kernel<<<grid, NTHREADS, smem_bytes>>>(img1, img2);
    ssim_finalize_kernel<<<1, 256>>>(out);
}